// round 17
// baseline (speedup 1.0000x reference)
#include <cuda_runtime.h>
#include <cuda_fp16.h>
#include <cstdint>

#define N_NODES 100000
#define N_EDGES 1600000
#define IN_CH   128
#define HEADS   4
#define OUT_CH  32
#define HC      128   // HEADS*OUT_CH

// ---------------- scratch (__device__ globals: no allocation allowed) ----------------
__device__ __align__(16) __half g_xh_h[N_NODES * HC];  // 25.6 MB fp16 messages
__device__ float g_si[N_NODES * HEADS];       // per-node dot with att_i (fp32)
__device__ float g_sj[N_NODES * HEADS];       // per-node dot with att_j (fp32)
__device__ int   g_count[N_NODES];            // in-degree (by dst = row)
__device__ int   g_start[N_NODES];            // CSR exclusive offsets
__device__ int   g_cursor[N_NODES];           // scatter cursors
// 32B per edge: [ex0 ex1 ex2 ex3][col pad pad pad] -> one L2 sector per edge
__device__ __align__(32) float4 g_edge[N_EDGES * 2];   // 51.2 MB
__device__ float g_we[HEADS];                 // (lin_edge_w ⊙ att_e) row sums
__device__ int   g_stride;                    // 1: int32 edge_index, 2: int64

#define SCAN_BLOCK 256
#define SCAN_ITEMS 4
#define SCAN_TILE  (SCAN_BLOCK * SCAN_ITEMS)
#define SCAN_NBLK  ((N_NODES + SCAN_TILE - 1) / SCAN_TILE)
__device__ int g_blocksums[SCAN_NBLK];

// ---- bit reinterpret helpers ----
__device__ __forceinline__ unsigned h2_as_u32(__half2 h) {
    return *reinterpret_cast<unsigned*>(&h);
}
__device__ __forceinline__ __half2 u32_as_h2(unsigned u) {
    return *reinterpret_cast<__half2*>(&u);
}

// ---------------- init: zero histogram, fold edge scalars, probe index dtype --------
__global__ void k_init(const float* __restrict__ lin_edge_w, const float* __restrict__ att,
                       const int* __restrict__ ei) {
    int t = blockIdx.x * blockDim.x + threadIdx.x;
    if (t < N_NODES) g_count[t] = 0;
    if (t < HEADS) {
        float s = 0.f;
        #pragma unroll
        for (int c = 0; c < OUT_CH; ++c)
            s += lin_edge_w[t * OUT_CH + c] * att[t * 3 * OUT_CH + 2 * OUT_CH + c];
        g_we[t] = s;
    }
    if (t == HEADS) {
        int allzero = 1;
        #pragma unroll 1
        for (int i = 0; i < 64; ++i)
            if (ei[2 * i + 1] != 0) { allzero = 0; break; }
        g_stride = allzero ? 2 : 1;
    }
}

// ---------------- GEMM via packed fp32x2 FMA (Blackwell FFMA2, PTX-only) -----------
// 64-row x 128-col tile, 128 threads. Accumulators packed along rows:
// acc2[i2][j] = {row 2*i2, row 2*i2+1} for col tx*8+j. A-pairs are free LDS.64 of
// adjacent xs rows... (adjacent row-strip floats); B values pre-DUPLICATED in smem
// (ws_d[k][j*32+2*tx] = {w,w}) so the inner loop is pure LDS.64 + fma.rn.f32x2.
__global__ void k_gemm(const float* __restrict__ x, const float* __restrict__ w,
                       const float* __restrict__ att) {
    __shared__ __align__(16) float xs[32][68];     // xs[k][r] (r = row in 64-row tile)
    __shared__ __align__(16) float ws_d[32][258];  // duplicated W: [k][(c&7)*32 + 2*(c>>3)]

    const int tid = threadIdx.x;            // 0..127
    const int tx  = tid & 15;               // col group -> cols tx*8..tx*8+7
    const int ty  = tid >> 4;               // row group -> rows ty*8..ty*8+7
    const int rowbase = blockIdx.x * 64;
    const int h   = tx >> 2;                // head of this thread's 8 columns
    const int cin = (tx & 3) * 8;           // col offset within head

    const float4* x4 = (const float4*)x;
    const float4* w4 = (const float4*)w;

    unsigned long long acc2[4][8];
    #pragma unroll
    for (int i2 = 0; i2 < 4; ++i2)
        #pragma unroll
        for (int j = 0; j < 8; ++j) acc2[i2][j] = 0ull;

    for (int kc = 0; kc < IN_CH; kc += 32) {
        // x tile: 64 rows x 32 k, transpose into xs[k][r]
        #pragma unroll
        for (int it = 0; it < 4; ++it) {
            int idx = tid + it * 128;           // 0..511
            int r = idx >> 3, q = idx & 7;
            int grow = rowbase + r;
            float4 v = make_float4(0.f, 0.f, 0.f, 0.f);
            if (grow < N_NODES) v = x4[grow * (IN_CH / 4) + (kc >> 2) + q];
            xs[q * 4 + 0][r] = v.x; xs[q * 4 + 1][r] = v.y;
            xs[q * 4 + 2][r] = v.z; xs[q * 4 + 3][r] = v.w;
        }
        // w tile: 128 cols x 32 k, store duplicated pairs {w,w}
        #pragma unroll
        for (int it = 0; it < 8; ++it) {
            int idx = tid + it * 128;           // 0..1023
            int c = idx >> 3, q = idx & 7;      // col, float4-chunk within 32 k
            float4 v = w4[c * (IN_CH / 4) + (kc >> 2) + q];
            int coff = (c & 7) * 32 + 2 * (c >> 3);
            *(float2*)&ws_d[q * 4 + 0][coff] = make_float2(v.x, v.x);
            *(float2*)&ws_d[q * 4 + 1][coff] = make_float2(v.y, v.y);
            *(float2*)&ws_d[q * 4 + 2][coff] = make_float2(v.z, v.z);
            *(float2*)&ws_d[q * 4 + 3][coff] = make_float2(v.w, v.w);
        }
        __syncthreads();

        #pragma unroll
        for (int k = 0; k < 32; ++k) {
            unsigned long long a2[4], b2[8];
            #pragma unroll
            for (int i2 = 0; i2 < 4; ++i2)
                a2[i2] = *(const unsigned long long*)&xs[k][ty * 8 + 2 * i2];
            #pragma unroll
            for (int j = 0; j < 8; ++j)
                b2[j] = *(const unsigned long long*)&ws_d[k][j * 32 + 2 * tx];
            #pragma unroll
            for (int i2 = 0; i2 < 4; ++i2)
                #pragma unroll
                for (int j = 0; j < 8; ++j)
                    asm("fma.rn.f32x2 %0, %1, %2, %0;"
                        : "+l"(acc2[i2][j]) : "l"(a2[i2]), "l"(b2[j]));
        }
        __syncthreads();
    }

    // unpack packed accumulators -> acc[row-in-strip][j]
    float acc[8][8];
    #pragma unroll
    for (int i2 = 0; i2 < 4; ++i2)
        #pragma unroll
        for (int j = 0; j < 8; ++j) {
            float lo, hi;
            asm("mov.b64 {%0, %1}, %2;" : "=f"(lo), "=f"(hi) : "l"(acc2[i2][j]));
            acc[2 * i2][j] = lo;
            acc[2 * i2 + 1][j] = hi;
        }

    // att coefficients for this thread's 8 columns
    float ai[8], aj[8];
    #pragma unroll
    for (int j = 0; j < 8; ++j) {
        ai[j] = att[h * 96 + cin + j];
        aj[j] = att[h * 96 + 32 + cin + j];
    }

    #pragma unroll
    for (int i = 0; i < 8; ++i) {
        int row = rowbase + ty * 8 + i;
        float si = 0.f, sj = 0.f;
        #pragma unroll
        for (int j = 0; j < 8; ++j) {
            si = fmaf(acc[i][j], ai[j], si);
            sj = fmaf(acc[i][j], aj[j], sj);
        }
        // quad reduce across the 4 threads covering this head
        si += __shfl_xor_sync(0xffffffffu, si, 1);
        si += __shfl_xor_sync(0xffffffffu, si, 2);
        sj += __shfl_xor_sync(0xffffffffu, sj, 1);
        sj += __shfl_xor_sync(0xffffffffu, sj, 2);

        if (row < N_NODES) {
            uint4 pk;
            pk.x = h2_as_u32(__floats2half2_rn(acc[i][0], acc[i][1]));
            pk.y = h2_as_u32(__floats2half2_rn(acc[i][2], acc[i][3]));
            pk.z = h2_as_u32(__floats2half2_rn(acc[i][4], acc[i][5]));
            pk.w = h2_as_u32(__floats2half2_rn(acc[i][6], acc[i][7]));
            *(uint4*)&g_xh_h[(size_t)row * HC + tx * 8] = pk;
            if ((tx & 3) == 0) {
                g_si[row * HEADS + h] = si;
                g_sj[row * HEADS + h] = sj;
            }
        }
    }
}

// ---------------- degree histogram (dst = row), 4 edges per thread ----------------
__global__ void k_degree(const int* __restrict__ ei32) {
    int base = 4 * (blockIdx.x * blockDim.x + threadIdx.x);
    int st = g_stride;
    int r[4];
    #pragma unroll
    for (int i = 0; i < 4; ++i) {
        int e = base + i;
        r[i] = (e < N_EDGES) ? ei32[(size_t)st * e] : -1;
    }
    #pragma unroll
    for (int i = 0; i < 4; ++i)
        if ((unsigned)r[i] < N_NODES) atomicAdd(&g_count[r[i]], 1);
}

// ---------------- 3-stage exclusive prefix sum over N counts ----------------
__global__ void k_scan1() {
    __shared__ int sh[SCAN_BLOCK];
    int base = blockIdx.x * SCAN_TILE + threadIdx.x * SCAN_ITEMS;
    int v[SCAN_ITEMS];
    int s = 0;
    #pragma unroll
    for (int i = 0; i < SCAN_ITEMS; ++i) {
        int idx = base + i;
        v[i] = (idx < N_NODES) ? g_count[idx] : 0;
        s += v[i];
    }
    sh[threadIdx.x] = s;
    __syncthreads();
    for (int off = 1; off < SCAN_BLOCK; off <<= 1) {
        int t = (threadIdx.x >= off) ? sh[threadIdx.x - off] : 0;
        __syncthreads();
        sh[threadIdx.x] += t;
        __syncthreads();
    }
    int excl = sh[threadIdx.x] - s;
    if (threadIdx.x == SCAN_BLOCK - 1) g_blocksums[blockIdx.x] = sh[SCAN_BLOCK - 1];
    int run = excl;
    #pragma unroll
    for (int i = 0; i < SCAN_ITEMS; ++i) {
        int idx = base + i;
        if (idx < N_NODES) g_start[idx] = run;
        run += v[i];
    }
}

__global__ void k_scan2() {
    if (threadIdx.x == 0 && blockIdx.x == 0) {
        int running = 0;
        for (int b = 0; b < SCAN_NBLK; ++b) {
            int t = g_blocksums[b];
            g_blocksums[b] = running;
            running += t;
        }
    }
}

__global__ void k_scan3() {
    int i = blockIdx.x * blockDim.x + threadIdx.x;
    if (i >= N_NODES) return;
    int st = g_start[i] + g_blocksums[i / SCAN_TILE];
    g_start[i]  = st;
    g_cursor[i] = st;
}

// ---------------- bucket scatter + logits + exp (no max shift needed) ----------------
__global__ void k_scatter(const float* __restrict__ edge_attr, const int* __restrict__ ei32) {
    int e = blockIdx.x * blockDim.x + threadIdx.x;
    if (e >= N_EDGES) return;
    int st = g_stride;
    int r = ei32[(size_t)st * e];
    int c = ei32[(size_t)st * (N_EDGES + e)];
    if ((unsigned)r >= N_NODES || (unsigned)c >= N_NODES) return;
    float ea = edge_attr[e];
    int pos = atomicAdd(&g_cursor[r], 1);
    float4 si = ((const float4*)g_si)[r];
    float4 sj = ((const float4*)g_sj)[c];
    float4 a;
    a.x = si.x + sj.x + ea * g_we[0];
    a.y = si.y + sj.y + ea * g_we[1];
    a.z = si.z + sj.z + ea * g_we[2];
    a.w = si.w + sj.w + ea * g_we[3];
    a.x = a.x > 0.f ? a.x : 0.2f * a.x;
    a.y = a.y > 0.f ? a.y : 0.2f * a.y;
    a.z = a.z > 0.f ? a.z : 0.2f * a.z;
    a.w = a.w > 0.f ? a.w : 0.2f * a.w;
    float4 ex;
    ex.x = __expf(fminf(a.x, 80.f));
    ex.y = __expf(fminf(a.y, 80.f));
    ex.z = __expf(fminf(a.z, 80.f));
    ex.w = __expf(fminf(a.w, 80.f));
    g_edge[2 * pos]     = ex;
    g_edge[2 * pos + 1] = make_float4(__int_as_float(c), 0.f, 0.f, 0.f);
}

// ---------------- per-node: sum(ex) + fp16 gather (warp per node) ----------------
__global__ void k_aggregate(float* __restrict__ out) {
    int gt = blockIdx.x * blockDim.x + threadIdx.x;
    int n = gt >> 5, lane = gt & 31;
    if (n >= N_NODES) return;
    int s   = g_start[n];
    int deg = g_count[n];
    const float4* eb = g_edge + 2 * (size_t)s;

    float4 sm = make_float4(0.f, 0.f, 0.f, 0.f);
    for (int j = lane; j < deg; j += 32) {
        float4 ex = __ldg(&eb[2 * j]);
        sm.x += ex.x; sm.y += ex.y; sm.z += ex.z; sm.w += ex.w;
    }
    #pragma unroll
    for (int o = 16; o >= 1; o >>= 1) {
        sm.x += __shfl_xor_sync(0xffffffffu, sm.x, o);
        sm.y += __shfl_xor_sync(0xffffffffu, sm.y, o);
        sm.z += __shfl_xor_sync(0xffffffffu, sm.z, o);
        sm.w += __shfl_xor_sync(0xffffffffu, sm.w, o);
    }
    int h = lane >> 3;
    float smh  = (h < 2) ? (h == 0 ? sm.x : sm.y) : (h == 2 ? sm.z : sm.w);
    float invh = 1.f / (smh + 1e-16f);

    float4 acc = make_float4(0.f, 0.f, 0.f, 0.f);
    const uint2*  xh2 = (const uint2*)g_xh_h;
    const float*  exs = (const float*)eb;
    #pragma unroll 2
    for (int j = 0; j < deg; ++j) {
        int   c  = __float_as_int(__ldg(&exs[8 * j + 4]));
        float w  = __ldg(&exs[8 * j + h]) * invh;
        uint2 raw = __ldg(&xh2[(size_t)c * 32 + lane]);
        float2 f0 = __half22float2(u32_as_h2(raw.x));
        float2 f1 = __half22float2(u32_as_h2(raw.y));
        acc.x = fmaf(w, f0.x, acc.x);
        acc.y = fmaf(w, f0.y, acc.y);
        acc.z = fmaf(w, f1.x, acc.z);
        acc.w = fmaf(w, f1.y, acc.w);
    }
    ((float4*)out)[n * (HC / 4) + lane] = acc;
}

// ---------------- launch ----------------
extern "C" void kernel_launch(void* const* d_in, const int* in_sizes, int n_in,
                              void* d_out, int out_size) {
    const float* x           = (const float*)d_in[0];
    const float* edge_attr   = (const float*)d_in[1];
    const int*   ei32        = (const int*)d_in[2];
    const float* lin_w       = (const float*)d_in[3];
    const float* lin_edge_w  = (const float*)d_in[4];
    const float* att         = (const float*)d_in[5];
    float* out = (float*)d_out;

    k_init   <<<(N_NODES + 255) / 256, 256>>>(lin_edge_w, att, ei32);
    k_gemm   <<<(N_NODES + 63) / 64, 128>>>(x, lin_w, att);
    k_degree <<<(N_EDGES / 4 + 255) / 256, 256>>>(ei32);
    k_scan1  <<<SCAN_NBLK, SCAN_BLOCK>>>();
    k_scan2  <<<1, 32>>>();
    k_scan3  <<<(N_NODES + 255) / 256, 256>>>();
    k_scatter<<<(N_EDGES + 255) / 256, 256>>>(edge_attr, ei32);
    k_aggregate<<<(N_NODES * 32 + 255) / 256, 256>>>(out);
}